// round 15
// baseline (speedup 1.0000x reference)
#include <cuda_runtime.h>
#include <cuda_bf16.h>
#include <cstdint>
#include <cstddef>

#define NSTEP 32768
#define HH 128
#define G3 384
#define KDIM 530
#define EDIM 512
#define ADIM 18
#define FCDIM 256

__device__ float g_gi_pred[(size_t)NSTEP * G3];
__device__ float g_gi_true[(size_t)NSTEP * G3];
__device__ float g_hpred[(size_t)NSTEP * HH];

typedef unsigned long long ull;

__device__ __forceinline__ ull ffma2(ull a, ull b, ull c) {
    ull d;
    asm("fma.rn.f32x2 %0, %1, %2, %3;" : "=l"(d) : "l"(a), "l"(b), "l"(c));
    return d;
}
__device__ __forceinline__ float plo(ull a) { return __uint_as_float((unsigned)a); }
__device__ __forceinline__ float phi(ull a) { return __uint_as_float((unsigned)(a >> 32)); }

__device__ __forceinline__ float tanh_a(float x) {
    float y;
    asm("tanh.approx.f32 %0, %1;" : "=f"(y) : "f"(x));
    return y;
}
__device__ __forceinline__ float sig_a(float x) {
    return fmaf(0.5f, tanh_a(0.5f * x), 0.5f);
}
__device__ __forceinline__ float sigf(float x) {
    return __fdividef(1.f, 1.f + __expf(-x));
}
__device__ __forceinline__ void cpa16(unsigned dst, const void* src) {
    asm volatile("cp.async.cg.shared.global [%0], [%1], 16;" :: "r"(dst), "l"(src));
}

// ============================================================================
// Kernel 1: gi = concat(enc, act) @ Wih.T + bih (+ bhh folded for r/z gates)
// BM=128, BN=64, BK=16, 256 thr, 8x4 micro-tile (L1-traffic-optimized).
// ============================================================================
__global__ void __launch_bounds__(256) gi_gemm(
    const float* __restrict__ encp, const float* __restrict__ enct,
    const float* __restrict__ act,  const float* __restrict__ Wih,
    const float* __restrict__ bih,  const float* __restrict__ bhh)
{
    const float* A = blockIdx.z ? enct : encp;
    float* C = blockIdx.z ? g_gi_true : g_gi_pred;

    __shared__ __align__(16) float As[16][132];
    __shared__ __align__(16) float Bs[16][68];

    int t = threadIdx.x;
    int m0 = blockIdx.x * 128, n0 = blockIdx.y * 64;
    int tx = t & 15, ty = t >> 4;            // compute: tx -> 4 N-cols, ty -> 8 M-rows
    int arow = t >> 1, acol = (t & 1) * 8;   // A loader: 8 floats (2x float4)
    int brow = t >> 2, bcol = (t & 3) * 4;   // B loader: 4 floats (2x float2)

    float acc[8][4];
#pragma unroll
    for (int a = 0; a < 8; a++)
#pragma unroll
        for (int b = 0; b < 4; b++) acc[a][b] = 0.f;

    for (int kt = 0; kt < 34; kt++) {
        int k0 = kt * 16;
        float av[8], bv[4];
        if (k0 < EDIM) {
            const float* ap = A + (size_t)(m0 + arow) * EDIM + k0 + acol;
            float4 u0 = *(const float4*)(ap);
            float4 u1 = *(const float4*)(ap + 4);
            av[0] = u0.x; av[1] = u0.y; av[2] = u0.z; av[3] = u0.w;
            av[4] = u1.x; av[5] = u1.y; av[6] = u1.z; av[7] = u1.w;
            const float* bp = Wih + (size_t)(n0 + brow) * KDIM + k0 + bcol;
            float2 v0 = *(const float2*)(bp);
            float2 v1 = *(const float2*)(bp + 2);
            bv[0] = v0.x; bv[1] = v0.y; bv[2] = v1.x; bv[3] = v1.y;
        } else {
#pragma unroll
            for (int j = 0; j < 8; j++) {
                int kg = k0 + acol + j;
                av[j] = (kg < KDIM) ? act[(size_t)(m0 + arow) * ADIM + (kg - EDIM)] : 0.f;
            }
#pragma unroll
            for (int j = 0; j < 4; j++) {
                int kg = k0 + bcol + j;
                bv[j] = (kg < KDIM) ? Wih[(size_t)(n0 + brow) * KDIM + kg] : 0.f;
            }
        }
        __syncthreads();
#pragma unroll
        for (int j = 0; j < 8; j++) As[acol + j][arow] = av[j];
#pragma unroll
        for (int j = 0; j < 4; j++) Bs[bcol + j][brow] = bv[j];
        __syncthreads();
#pragma unroll
        for (int kk = 0; kk < 16; kk++) {
            float4 a0 = *(const float4*)&As[kk][ty * 8];
            float4 a1 = *(const float4*)&As[kk][ty * 8 + 4];
            float4 b4 = *(const float4*)&Bs[kk][tx * 4];
            float ar[8] = {a0.x, a0.y, a0.z, a0.w, a1.x, a1.y, a1.z, a1.w};
            float br_[4] = {b4.x, b4.y, b4.z, b4.w};
#pragma unroll
            for (int r = 0; r < 8; r++)
#pragma unroll
                for (int cc = 0; cc < 4; cc++) acc[r][cc] += ar[r] * br_[cc];
        }
    }

    // epilogue: bias = bih + (bhh folded for r/z gates only: n < 2H)
    float bias[4];
#pragma unroll
    for (int cc = 0; cc < 4; cc++) {
        int n = n0 + tx * 4 + cc;
        bias[cc] = bih[n] + ((n < 2 * HH) ? bhh[n] : 0.f);
    }
#pragma unroll
    for (int r = 0; r < 8; r++) {
        int m = m0 + ty * 8 + r;
#pragma unroll
        for (int cc = 0; cc < 4; cc++) {
            int n = n0 + tx * 4 + cc;
            C[(size_t)m * G3 + n] = acc[r][cc] + bias[cc];
        }
    }
}

// ============================================================================
// Kernel 2: GRU scan — champion architecture (R10/R13), r/z bhh pre-folded.
// 256 thr, two-lane split, FFMA2 matvec, 1 shfl level, 1 bar/step, 16B ring.
// ============================================================================
__global__ void __launch_bounds__(256, 1) gru_scan(
    const float* __restrict__ Whh, const float* __restrict__ bhh,
    const float* __restrict__ h0)
{
    __shared__ __align__(16) float ring[4][768];   // [pred 384 | true 384] per slot
    __shared__ __align__(16) float hbuf[2][HH];

    int t = threadIdx.x;
    int i = t >> 1;
    int c = t & 1;

    // Register-resident weights: 3 gates x 64 contiguous columns = 96 ull
    ull wr[32], wz[32], wn[32];
    {
        const ull* pr = (const ull*)(Whh + (size_t)i * HH + c * 64);
        const ull* pz = (const ull*)(Whh + (size_t)(HH + i) * HH + c * 64);
        const ull* pn = (const ull*)(Whh + (size_t)(2 * HH + i) * HH + c * 64);
#pragma unroll
        for (int q = 0; q < 32; q++) { wr[q] = pr[q]; wz[q] = pz[q]; wn[q] = pn[q]; }
    }
    float bn = bhh[2 * HH + i];   // n-gate bias stays (inside r multiplication)
    if (t < HH) hbuf[0][t] = h0[t];

    // ---- Ring prefill: slots 0,1,2 (16B cp.async, threads 0..191) ----
#pragma unroll
    for (int k = 0; k < 3; k++) {
        unsigned dst = (unsigned)__cvta_generic_to_shared(&ring[k][0]);
        if (t < 96) cpa16(dst + t * 16, (const char*)(g_gi_pred + (size_t)k * G3) + t * 16);
        else if (t < 192) cpa16(dst + 1536 + (t - 96) * 16,
                                (const char*)(g_gi_true + (size_t)k * G3) + (t - 96) * 16);
        asm volatile("cp.async.commit_group;");
    }
    asm volatile("cp.async.wait_group 2;" ::: "memory");
    __syncthreads();

    for (int s = 0; s < NSTEP; s++) {
        // ---- issue prefetch for slot s+3 ----
        if (s + 3 < NSTEP) {
            unsigned dst = (unsigned)__cvta_generic_to_shared(&ring[(s + 3) & 3][0]);
            if (t < 96) cpa16(dst + t * 16, (const char*)(g_gi_pred + (size_t)(s + 3) * G3) + t * 16);
            else if (t < 192) cpa16(dst + 1536 + (t - 96) * 16,
                                    (const char*)(g_gi_true + (size_t)(s + 3) * G3) + (t - 96) * 16);
        }
        asm volatile("cp.async.commit_group;");

        // ---- ring loads for this step (latency hidden under matvec) ----
        const float* gb = &ring[s & 3][c * 384];
        float g0 = gb[i], g1 = gb[HH + i], g2 = gb[2 * HH + i];

        // ---- matvec: gh partial over this thread's 64 columns ----
        const ulonglong2* hp2 = (const ulonglong2*)(hbuf[s & 1] + c * 64);
        ull ar = 0, az = 0, an = 0;
#pragma unroll
        for (int q = 0; q < 16; q++) {
            ulonglong2 hq = hp2[q];
            ar = ffma2(wr[2 * q],     hq.x, ar);
            az = ffma2(wz[2 * q],     hq.x, az);
            an = ffma2(wn[2 * q],     hq.x, an);
            ar = ffma2(wr[2 * q + 1], hq.y, ar);
            az = ffma2(wz[2 * q + 1], hq.y, az);
            an = ffma2(wn[2 * q + 1], hq.y, an);
        }
        float sr = plo(ar) + phi(ar);
        float sn = plo(an) + phi(an);
        float sz = plo(az) + phi(az);
        sr += __shfl_xor_sync(0xffffffffu, sr, 1);
        sn += __shfl_xor_sync(0xffffffffu, sn, 1);
        sz += __shfl_xor_sync(0xffffffffu, sz, 1);

        // ---- symmetric GRU update (c==0: pred->out, c==1: true->state) ----
        // g0/g1 already carry bih + bhh (r/z); g2 carries bih only.
        float hprev = hbuf[s & 1][i];
        float r = sig_a(g0 + sr);
        float z = sig_a(g1 + sz);
        float n = tanh_a(g2 + r * (sn + bn));
        float hnew = (1.f - z) * n + z * hprev;
        if (c) hbuf[(s + 1) & 1][i] = hnew;
        else   g_hpred[(size_t)s * HH + i] = hnew;

        asm volatile("cp.async.wait_group 2;" ::: "memory");
        __syncthreads();
    }
}

// ============================================================================
// Kernel 3: MLP head (unchanged, proven)
// ============================================================================
__global__ void __launch_bounds__(256) mlp_head(
    const float* __restrict__ fc1w, const float* __restrict__ fc1b,
    const float* __restrict__ fc2w, const float* __restrict__ fc2b,
    float* __restrict__ out)
{
    extern __shared__ float sm[];
    float* w1  = sm;
    float* b1  = sm + FCDIM * HH;
    float* w2  = b1 + FCDIM;
    float* hs  = w2 + FCDIM;
    float* red = hs + HH;

    int t = threadIdx.x;
    for (int idx = t; idx < FCDIM * HH; idx += 256) w1[idx] = fc1w[idx];
    b1[t] = fc1b[t];
    w2[t] = fc2w[t];
    __syncthreads();

    float myb = b1[t], myw2 = w2[t];
    const float4* wj = (const float4*)(w1 + t * HH);

    for (int r = 0; r < 64; r++) {
        size_t row = (size_t)blockIdx.x * 64 + r;
        if (t < HH) hs[t] = g_hpred[row * HH + t];
        __syncthreads();
        float acc = 0.f;
        const float4* hv = (const float4*)hs;
#pragma unroll
        for (int q = 0; q < 32; q++) {
            float4 a = wj[q], b = hv[q];
            acc += a.x * b.x; acc += a.y * b.y; acc += a.z * b.z; acc += a.w * b.w;
        }
        float v = acc + myb;
        v = v > 0.f ? v : 0.f;
        v *= myw2;
#pragma unroll
        for (int m = 16; m; m >>= 1) v += __shfl_xor_sync(0xffffffffu, v, m);
        if ((t & 31) == 0) red[t >> 5] = v;
        __syncthreads();
        if (t == 0) {
            float sv = red[0] + red[1] + red[2] + red[3] +
                       red[4] + red[5] + red[6] + red[7] + fc2b[0];
            out[row] = sigf(sv);
        }
        __syncthreads();
    }
}

extern "C" void kernel_launch(void* const* d_in, const int* in_sizes, int n_in,
                              void* d_out, int out_size) {
    const float* enc  = (const float*)d_in[0];
    const float* act  = (const float*)d_in[1];
    const float* tru  = (const float*)d_in[2];
    const float* Wih  = (const float*)d_in[3];
    const float* Whh  = (const float*)d_in[4];
    const float* bih  = (const float*)d_in[5];
    const float* bhh  = (const float*)d_in[6];
    const float* h0   = (const float*)d_in[7];
    const float* fc1w = (const float*)d_in[8];
    const float* fc1b = (const float*)d_in[9];
    const float* fc2w = (const float*)d_in[10];
    const float* fc2b = (const float*)d_in[11];
    float* out = (float*)d_out;

    int mlp_smem = (FCDIM * HH + FCDIM + FCDIM + HH + 8) * 4;
    cudaFuncSetAttribute(mlp_head, cudaFuncAttributeMaxDynamicSharedMemorySize, mlp_smem);

    dim3 g(256, 6, 2);
    gi_gemm<<<g, 256>>>(enc, tru, act, Wih, bih, bhh);
    gru_scan<<<1, 256>>>(Whh, bhh, h0);
    mlp_head<<<512, 256, mlp_smem>>>(fc1w, fc1b, fc2w, fc2b, out);
}

// round 16
// speedup vs baseline: 1.6509x; 1.6509x over previous
#include <cuda_runtime.h>
#include <cuda_bf16.h>
#include <cstdint>
#include <cstddef>

#define NSTEP 32768
#define HH 128
#define G3 384
#define KDIM 530
#define EDIM 512
#define ADIM 18
#define FCDIM 256

__device__ float g_gi_pred[(size_t)NSTEP * G3];
__device__ float g_gi_true[(size_t)NSTEP * G3];
__device__ float g_hpred[(size_t)NSTEP * HH];

typedef unsigned long long ull;

__device__ __forceinline__ ull ffma2(ull a, ull b, ull c) {
    ull d;
    asm("fma.rn.f32x2 %0, %1, %2, %3;" : "=l"(d) : "l"(a), "l"(b), "l"(c));
    return d;
}
__device__ __forceinline__ float plo(ull a) { return __uint_as_float((unsigned)a); }
__device__ __forceinline__ float phi(ull a) { return __uint_as_float((unsigned)(a >> 32)); }

__device__ __forceinline__ float tanh_a(float x) {
    float y;
    asm("tanh.approx.f32 %0, %1;" : "=f"(y) : "f"(x));
    return y;
}
__device__ __forceinline__ float sig_a(float x) {
    return fmaf(0.5f, tanh_a(0.5f * x), 0.5f);
}
__device__ __forceinline__ float sigf(float x) {
    return __fdividef(1.f, 1.f + __expf(-x));
}
__device__ __forceinline__ void cpa16(unsigned dst, const void* src) {
    asm volatile("cp.async.cg.shared.global [%0], [%1], 16;" :: "r"(dst), "l"(src));
}

// ============================================================================
// Kernel 1: gi = concat(enc, act) @ Wih.T + bih (+ bhh folded for r/z gates)
// PROVEN 64x64/BK=16/4x4 tile (R3-R13 champion gemm); only the epilogue bias
// line changed.
// ============================================================================
__global__ void __launch_bounds__(256) gi_gemm(
    const float* __restrict__ encp, const float* __restrict__ enct,
    const float* __restrict__ act,  const float* __restrict__ Wih,
    const float* __restrict__ bih,  const float* __restrict__ bhh)
{
    const float* A = blockIdx.z ? enct : encp;
    float* C = blockIdx.z ? g_gi_true : g_gi_pred;

    __shared__ __align__(16) float As[16][68];
    __shared__ __align__(16) float Bs[16][68];

    int t = threadIdx.x;
    int m0 = blockIdx.x * 64, n0 = blockIdx.y * 64;
    int tx = t & 15, ty = t >> 4;
    int arow = t >> 2, ac4 = (t & 3) * 4;

    float acc[4][4];
#pragma unroll
    for (int a = 0; a < 4; a++)
#pragma unroll
        for (int b = 0; b < 4; b++) acc[a][b] = 0.f;

    for (int kt = 0; kt < 34; kt++) {
        int k0 = kt * 16;
        float av[4], bv[4];
        if (k0 < EDIM) {
            float4 v = *(const float4*)(A + (size_t)(m0 + arow) * EDIM + k0 + ac4);
            av[0] = v.x; av[1] = v.y; av[2] = v.z; av[3] = v.w;
            const float* bp = Wih + (size_t)(n0 + arow) * KDIM + k0 + ac4;
            float2 u0 = *(const float2*)(bp);
            float2 u1 = *(const float2*)(bp + 2);
            bv[0] = u0.x; bv[1] = u0.y; bv[2] = u1.x; bv[3] = u1.y;
        } else {
#pragma unroll
            for (int j = 0; j < 4; j++) {
                int kg = k0 + ac4 + j;
                av[j] = (kg < KDIM) ? act[(size_t)(m0 + arow) * ADIM + (kg - EDIM)] : 0.f;
                bv[j] = (kg < KDIM) ? Wih[(size_t)(n0 + arow) * KDIM + kg] : 0.f;
            }
        }
        __syncthreads();
#pragma unroll
        for (int j = 0; j < 4; j++) { As[ac4 + j][arow] = av[j]; Bs[ac4 + j][arow] = bv[j]; }
        __syncthreads();
#pragma unroll
        for (int kk = 0; kk < 16; kk++) {
            float4 a4 = *(const float4*)&As[kk][ty * 4];
            float4 b4 = *(const float4*)&Bs[kk][tx * 4];
            float ar[4] = {a4.x, a4.y, a4.z, a4.w};
            float br[4] = {b4.x, b4.y, b4.z, b4.w};
#pragma unroll
            for (int r = 0; r < 4; r++)
#pragma unroll
                for (int cc = 0; cc < 4; cc++) acc[r][cc] += ar[r] * br[cc];
        }
    }
#pragma unroll
    for (int r = 0; r < 4; r++) {
        int m = m0 + ty * 4 + r;
#pragma unroll
        for (int cc = 0; cc < 4; cc++) {
            int n = n0 + tx * 4 + cc;
            float bias = bih[n] + ((n < 2 * HH) ? bhh[n] : 0.f);
            C[(size_t)m * G3 + n] = acc[r][cc] + bias;
        }
    }
}

// ============================================================================
// Kernel 2: GRU scan — champion architecture, r/z bhh pre-folded in gemm.
// 256 thr, two-lane split, FFMA2 matvec, 1 shfl level, 1 bar/step, 16B ring.
// ============================================================================
__global__ void __launch_bounds__(256, 1) gru_scan(
    const float* __restrict__ Whh, const float* __restrict__ bhh,
    const float* __restrict__ h0)
{
    __shared__ __align__(16) float ring[4][768];   // [pred 384 | true 384] per slot
    __shared__ __align__(16) float hbuf[2][HH];

    int t = threadIdx.x;
    int i = t >> 1;
    int c = t & 1;

    // Register-resident weights: 3 gates x 64 contiguous columns = 96 ull
    ull wr[32], wz[32], wn[32];
    {
        const ull* pr = (const ull*)(Whh + (size_t)i * HH + c * 64);
        const ull* pz = (const ull*)(Whh + (size_t)(HH + i) * HH + c * 64);
        const ull* pn = (const ull*)(Whh + (size_t)(2 * HH + i) * HH + c * 64);
#pragma unroll
        for (int q = 0; q < 32; q++) { wr[q] = pr[q]; wz[q] = pz[q]; wn[q] = pn[q]; }
    }
    float bn = bhh[2 * HH + i];   // n-gate bias stays (inside r multiplication)
    if (t < HH) hbuf[0][t] = h0[t];

    // ---- Ring prefill: slots 0,1,2 (16B cp.async, threads 0..191) ----
#pragma unroll
    for (int k = 0; k < 3; k++) {
        unsigned dst = (unsigned)__cvta_generic_to_shared(&ring[k][0]);
        if (t < 96) cpa16(dst + t * 16, (const char*)(g_gi_pred + (size_t)k * G3) + t * 16);
        else if (t < 192) cpa16(dst + 1536 + (t - 96) * 16,
                                (const char*)(g_gi_true + (size_t)k * G3) + (t - 96) * 16);
        asm volatile("cp.async.commit_group;");
    }
    asm volatile("cp.async.wait_group 2;" ::: "memory");
    __syncthreads();

    for (int s = 0; s < NSTEP; s++) {
        // ---- issue prefetch for slot s+3 ----
        if (s + 3 < NSTEP) {
            unsigned dst = (unsigned)__cvta_generic_to_shared(&ring[(s + 3) & 3][0]);
            if (t < 96) cpa16(dst + t * 16, (const char*)(g_gi_pred + (size_t)(s + 3) * G3) + t * 16);
            else if (t < 192) cpa16(dst + 1536 + (t - 96) * 16,
                                    (const char*)(g_gi_true + (size_t)(s + 3) * G3) + (t - 96) * 16);
        }
        asm volatile("cp.async.commit_group;");

        // ---- ring loads for this step (latency hidden under matvec) ----
        const float* gb = &ring[s & 3][c * 384];
        float g0 = gb[i], g1 = gb[HH + i], g2 = gb[2 * HH + i];

        // ---- matvec: gh partial over this thread's 64 columns ----
        const ulonglong2* hp2 = (const ulonglong2*)(hbuf[s & 1] + c * 64);
        ull ar = 0, az = 0, an = 0;
#pragma unroll
        for (int q = 0; q < 16; q++) {
            ulonglong2 hq = hp2[q];
            ar = ffma2(wr[2 * q],     hq.x, ar);
            az = ffma2(wz[2 * q],     hq.x, az);
            an = ffma2(wn[2 * q],     hq.x, an);
            ar = ffma2(wr[2 * q + 1], hq.y, ar);
            az = ffma2(wz[2 * q + 1], hq.y, az);
            an = ffma2(wn[2 * q + 1], hq.y, an);
        }
        float sr = plo(ar) + phi(ar);
        float sn = plo(an) + phi(an);
        float sz = plo(az) + phi(az);
        sr += __shfl_xor_sync(0xffffffffu, sr, 1);
        sn += __shfl_xor_sync(0xffffffffu, sn, 1);
        sz += __shfl_xor_sync(0xffffffffu, sz, 1);

        // ---- symmetric GRU update (c==0: pred->out, c==1: true->state) ----
        // g0/g1 already carry bih + bhh (r/z); g2 carries bih only.
        float hprev = hbuf[s & 1][i];
        float r = sig_a(g0 + sr);
        float z = sig_a(g1 + sz);
        float n = tanh_a(g2 + r * (sn + bn));
        float hnew = (1.f - z) * n + z * hprev;
        if (c) hbuf[(s + 1) & 1][i] = hnew;
        else   g_hpred[(size_t)s * HH + i] = hnew;

        asm volatile("cp.async.wait_group 2;" ::: "memory");
        __syncthreads();
    }
}

// ============================================================================
// Kernel 3: MLP head (unchanged, proven)
// ============================================================================
__global__ void __launch_bounds__(256) mlp_head(
    const float* __restrict__ fc1w, const float* __restrict__ fc1b,
    const float* __restrict__ fc2w, const float* __restrict__ fc2b,
    float* __restrict__ out)
{
    extern __shared__ float sm[];
    float* w1  = sm;
    float* b1  = sm + FCDIM * HH;
    float* w2  = b1 + FCDIM;
    float* hs  = w2 + FCDIM;
    float* red = hs + HH;

    int t = threadIdx.x;
    for (int idx = t; idx < FCDIM * HH; idx += 256) w1[idx] = fc1w[idx];
    b1[t] = fc1b[t];
    w2[t] = fc2w[t];
    __syncthreads();

    float myb = b1[t], myw2 = w2[t];
    const float4* wj = (const float4*)(w1 + t * HH);

    for (int r = 0; r < 64; r++) {
        size_t row = (size_t)blockIdx.x * 64 + r;
        if (t < HH) hs[t] = g_hpred[row * HH + t];
        __syncthreads();
        float acc = 0.f;
        const float4* hv = (const float4*)hs;
#pragma unroll
        for (int q = 0; q < 32; q++) {
            float4 a = wj[q], b = hv[q];
            acc += a.x * b.x; acc += a.y * b.y; acc += a.z * b.z; acc += a.w * b.w;
        }
        float v = acc + myb;
        v = v > 0.f ? v : 0.f;
        v *= myw2;
#pragma unroll
        for (int m = 16; m; m >>= 1) v += __shfl_xor_sync(0xffffffffu, v, m);
        if ((t & 31) == 0) red[t >> 5] = v;
        __syncthreads();
        if (t == 0) {
            float sv = red[0] + red[1] + red[2] + red[3] +
                       red[4] + red[5] + red[6] + red[7] + fc2b[0];
            out[row] = sigf(sv);
        }
        __syncthreads();
    }
}

extern "C" void kernel_launch(void* const* d_in, const int* in_sizes, int n_in,
                              void* d_out, int out_size) {
    const float* enc  = (const float*)d_in[0];
    const float* act  = (const float*)d_in[1];
    const float* tru  = (const float*)d_in[2];
    const float* Wih  = (const float*)d_in[3];
    const float* Whh  = (const float*)d_in[4];
    const float* bih  = (const float*)d_in[5];
    const float* bhh  = (const float*)d_in[6];
    const float* h0   = (const float*)d_in[7];
    const float* fc1w = (const float*)d_in[8];
    const float* fc1b = (const float*)d_in[9];
    const float* fc2w = (const float*)d_in[10];
    const float* fc2b = (const float*)d_in[11];
    float* out = (float*)d_out;

    int mlp_smem = (FCDIM * HH + FCDIM + FCDIM + HH + 8) * 4;
    cudaFuncSetAttribute(mlp_head, cudaFuncAttributeMaxDynamicSharedMemorySize, mlp_smem);

    dim3 g(512, 6, 2);
    gi_gemm<<<g, 256>>>(enc, tru, act, Wih, bih, bhh);
    gru_scan<<<1, 256>>>(Whh, bhh, h0);
    mlp_head<<<512, 256, mlp_smem>>>(fc1w, fc1b, fc2w, fc2b, out);
}

// round 17
// speedup vs baseline: 1.6616x; 1.0065x over previous
#include <cuda_runtime.h>
#include <cuda_bf16.h>
#include <cstdint>
#include <cstddef>

#define NSTEP 32768
#define HH 128
#define G3 384
#define KDIM 530
#define EDIM 512
#define ADIM 18
#define FCDIM 256

__device__ float g_gi_pred[(size_t)NSTEP * G3];
__device__ float g_gi_true[(size_t)NSTEP * G3];
__device__ float g_hpred[(size_t)NSTEP * HH];

typedef unsigned long long ull;

__device__ __forceinline__ ull ffma2(ull a, ull b, ull c) {
    ull d;
    asm("fma.rn.f32x2 %0, %1, %2, %3;" : "=l"(d) : "l"(a), "l"(b), "l"(c));
    return d;
}
__device__ __forceinline__ float plo(ull a) { return __uint_as_float((unsigned)a); }
__device__ __forceinline__ float phi(ull a) { return __uint_as_float((unsigned)(a >> 32)); }

__device__ __forceinline__ float tanh_a(float x) {
    float y;
    asm("tanh.approx.f32 %0, %1;" : "=f"(y) : "f"(x));
    return y;
}
__device__ __forceinline__ float sigf(float x) {
    return __fdividef(1.f, 1.f + __expf(-x));
}
__device__ __forceinline__ void cpa16(unsigned dst, const void* src) {
    asm volatile("cp.async.cg.shared.global [%0], [%1], 16;" :: "r"(dst), "l"(src));
}

// ============================================================================
// Kernel 1: gi = concat(enc, act) @ Wih.T + bih (+ bhh folded for r/z gates)
// Proven 64x64/BK=16/4x4 tile. (byte-identical to R16)
// ============================================================================
__global__ void __launch_bounds__(256) gi_gemm(
    const float* __restrict__ encp, const float* __restrict__ enct,
    const float* __restrict__ act,  const float* __restrict__ Wih,
    const float* __restrict__ bih,  const float* __restrict__ bhh)
{
    const float* A = blockIdx.z ? enct : encp;
    float* C = blockIdx.z ? g_gi_true : g_gi_pred;

    __shared__ __align__(16) float As[16][68];
    __shared__ __align__(16) float Bs[16][68];

    int t = threadIdx.x;
    int m0 = blockIdx.x * 64, n0 = blockIdx.y * 64;
    int tx = t & 15, ty = t >> 4;
    int arow = t >> 2, ac4 = (t & 3) * 4;

    float acc[4][4];
#pragma unroll
    for (int a = 0; a < 4; a++)
#pragma unroll
        for (int b = 0; b < 4; b++) acc[a][b] = 0.f;

    for (int kt = 0; kt < 34; kt++) {
        int k0 = kt * 16;
        float av[4], bv[4];
        if (k0 < EDIM) {
            float4 v = *(const float4*)(A + (size_t)(m0 + arow) * EDIM + k0 + ac4);
            av[0] = v.x; av[1] = v.y; av[2] = v.z; av[3] = v.w;
            const float* bp = Wih + (size_t)(n0 + arow) * KDIM + k0 + ac4;
            float2 u0 = *(const float2*)(bp);
            float2 u1 = *(const float2*)(bp + 2);
            bv[0] = u0.x; bv[1] = u0.y; bv[2] = u1.x; bv[3] = u1.y;
        } else {
#pragma unroll
            for (int j = 0; j < 4; j++) {
                int kg = k0 + ac4 + j;
                av[j] = (kg < KDIM) ? act[(size_t)(m0 + arow) * ADIM + (kg - EDIM)] : 0.f;
                bv[j] = (kg < KDIM) ? Wih[(size_t)(n0 + arow) * KDIM + kg] : 0.f;
            }
        }
        __syncthreads();
#pragma unroll
        for (int j = 0; j < 4; j++) { As[ac4 + j][arow] = av[j]; Bs[ac4 + j][arow] = bv[j]; }
        __syncthreads();
#pragma unroll
        for (int kk = 0; kk < 16; kk++) {
            float4 a4 = *(const float4*)&As[kk][ty * 4];
            float4 b4 = *(const float4*)&Bs[kk][tx * 4];
            float ar[4] = {a4.x, a4.y, a4.z, a4.w};
            float br[4] = {b4.x, b4.y, b4.z, b4.w};
#pragma unroll
            for (int r = 0; r < 4; r++)
#pragma unroll
                for (int cc = 0; cc < 4; cc++) acc[r][cc] += ar[r] * br[cc];
        }
    }
#pragma unroll
    for (int r = 0; r < 4; r++) {
        int m = m0 + ty * 4 + r;
#pragma unroll
        for (int cc = 0; cc < 4; cc++) {
            int n = n0 + tx * 4 + cc;
            float bias = bih[n] + ((n < 2 * HH) ? bhh[n] : 0.f);
            C[(size_t)m * G3 + n] = acc[r][cc] + bias;
        }
    }
}

// ============================================================================
// Kernel 2: GRU scan — champion architecture; activation chain restructured
// so all affine terms are precomputed off the serial dependency chain.
//   r-chain: FMA -> MUFU -> FMA -> MUFU -> 2 FMA -> STS  (~50 cyc post-shfl)
// ============================================================================
__global__ void __launch_bounds__(256, 1) gru_scan(
    const float* __restrict__ Whh, const float* __restrict__ bhh,
    const float* __restrict__ h0)
{
    __shared__ __align__(16) float ring[4][768];   // [pred 384 | true 384] per slot
    __shared__ __align__(16) float hbuf[2][HH];

    int t = threadIdx.x;
    int i = t >> 1;
    int c = t & 1;

    // Register-resident weights: 3 gates x 64 contiguous columns = 96 ull
    ull wr[32], wz[32], wn[32];
    {
        const ull* pr = (const ull*)(Whh + (size_t)i * HH + c * 64);
        const ull* pz = (const ull*)(Whh + (size_t)(HH + i) * HH + c * 64);
        const ull* pn = (const ull*)(Whh + (size_t)(2 * HH + i) * HH + c * 64);
#pragma unroll
        for (int q = 0; q < 32; q++) { wr[q] = pr[q]; wz[q] = pz[q]; wn[q] = pn[q]; }
    }
    float hbn = 0.5f * bhh[2 * HH + i];   // n-gate bias (halved; used in hX)
    if (t < HH) hbuf[0][t] = h0[t];

    // ---- Ring prefill: slots 0,1,2 (16B cp.async, threads 0..191) ----
#pragma unroll
    for (int k = 0; k < 3; k++) {
        unsigned dst = (unsigned)__cvta_generic_to_shared(&ring[k][0]);
        if (t < 96) cpa16(dst + t * 16, (const char*)(g_gi_pred + (size_t)k * G3) + t * 16);
        else if (t < 192) cpa16(dst + 1536 + (t - 96) * 16,
                                (const char*)(g_gi_true + (size_t)k * G3) + (t - 96) * 16);
        asm volatile("cp.async.commit_group;");
    }
    asm volatile("cp.async.wait_group 2;" ::: "memory");
    __syncthreads();

    for (int s = 0; s < NSTEP; s++) {
        // ---- issue prefetch for slot s+3 ----
        if (s + 3 < NSTEP) {
            unsigned dst = (unsigned)__cvta_generic_to_shared(&ring[(s + 3) & 3][0]);
            if (t < 96) cpa16(dst + t * 16, (const char*)(g_gi_pred + (size_t)(s + 3) * G3) + t * 16);
            else if (t < 192) cpa16(dst + 1536 + (t - 96) * 16,
                                    (const char*)(g_gi_true + (size_t)(s + 3) * G3) + (t - 96) * 16);
        }
        asm volatile("cp.async.commit_group;");

        // ---- ring loads + off-chain precomputes (hidden under matvec) ----
        const float* gb = &ring[s & 3][c * 384];
        float hg0 = 0.5f * gb[i];          // 0.5*g_r  (g carries bih+bhh for r/z)
        float hg1 = 0.5f * gb[HH + i];     // 0.5*g_z
        float g2  = gb[2 * HH + i];        // g_n (bih only)
        float hprev = hbuf[s & 1][i];
        float hp_half = 0.5f * hprev;

        // ---- matvec: gh partial over this thread's 64 columns ----
        const ulonglong2* hp2 = (const ulonglong2*)(hbuf[s & 1] + c * 64);
        ull ar = 0, az = 0, an = 0;
#pragma unroll
        for (int q = 0; q < 16; q++) {
            ulonglong2 hq = hp2[q];
            ar = ffma2(wr[2 * q],     hq.x, ar);
            az = ffma2(wz[2 * q],     hq.x, az);
            an = ffma2(wn[2 * q],     hq.x, an);
            ar = ffma2(wr[2 * q + 1], hq.y, ar);
            az = ffma2(wz[2 * q + 1], hq.y, az);
            an = ffma2(wn[2 * q + 1], hq.y, an);
        }
        float sr = plo(ar) + phi(ar);
        float sn = plo(an) + phi(an);
        float sz = plo(az) + phi(az);
        sr += __shfl_xor_sync(0xffffffffu, sr, 1);
        sn += __shfl_xor_sync(0xffffffffu, sn, 1);
        sz += __shfl_xor_sync(0xffffffffu, sz, 1);

        // ---- restructured GRU update (c==0: pred->out, c==1: true->state) ----
        // hX = 0.5*(sn+bn); n = tanh(g2 + r*(sn+bn)) with r = 0.5*th_r+0.5:
        //   n = tanh(fma(th_r, hX, g2+hX))
        // z-blend: hnew = 0.5*(n+hprev) + th_z*0.5*(hprev-n)
        float hX = fmaf(0.5f, sn, hbn);            // off r-chain (dep: sn shfl)
        float cn = g2 + hX;                        // off r-chain
        float th_r = tanh_a(fmaf(0.5f, sr, hg0));  // chain: FMA, MUFU
        float th_z = tanh_a(fmaf(0.5f, sz, hg1));  // parallel MUFU
        float n = tanh_a(fmaf(th_r, hX, cn));      // chain: FMA, MUFU
        float A_ = fmaf(0.5f, n, hp_half);         // 0.5*(n+hprev)
        float B_ = fmaf(-0.5f, n, hp_half);        // 0.5*(hprev-n)
        float hnew = fmaf(th_z, B_, A_);
        if (c) hbuf[(s + 1) & 1][i] = hnew;
        else   g_hpred[(size_t)s * HH + i] = hnew;

        asm volatile("cp.async.wait_group 2;" ::: "memory");
        __syncthreads();
    }
}

// ============================================================================
// Kernel 3: MLP head (unchanged, proven)
// ============================================================================
__global__ void __launch_bounds__(256) mlp_head(
    const float* __restrict__ fc1w, const float* __restrict__ fc1b,
    const float* __restrict__ fc2w, const float* __restrict__ fc2b,
    float* __restrict__ out)
{
    extern __shared__ float sm[];
    float* w1  = sm;
    float* b1  = sm + FCDIM * HH;
    float* w2  = b1 + FCDIM;
    float* hs  = w2 + FCDIM;
    float* red = hs + HH;

    int t = threadIdx.x;
    for (int idx = t; idx < FCDIM * HH; idx += 256) w1[idx] = fc1w[idx];
    b1[t] = fc1b[t];
    w2[t] = fc2w[t];
    __syncthreads();

    float myb = b1[t], myw2 = w2[t];
    const float4* wj = (const float4*)(w1 + t * HH);

    for (int r = 0; r < 64; r++) {
        size_t row = (size_t)blockIdx.x * 64 + r;
        if (t < HH) hs[t] = g_hpred[row * HH + t];
        __syncthreads();
        float acc = 0.f;
        const float4* hv = (const float4*)hs;
#pragma unroll
        for (int q = 0; q < 32; q++) {
            float4 a = wj[q], b = hv[q];
            acc += a.x * b.x; acc += a.y * b.y; acc += a.z * b.z; acc += a.w * b.w;
        }
        float v = acc + myb;
        v = v > 0.f ? v : 0.f;
        v *= myw2;
#pragma unroll
        for (int m = 16; m; m >>= 1) v += __shfl_xor_sync(0xffffffffu, v, m);
        if ((t & 31) == 0) red[t >> 5] = v;
        __syncthreads();
        if (t == 0) {
            float sv = red[0] + red[1] + red[2] + red[3] +
                       red[4] + red[5] + red[6] + red[7] + fc2b[0];
            out[row] = sigf(sv);
        }
        __syncthreads();
    }
}

extern "C" void kernel_launch(void* const* d_in, const int* in_sizes, int n_in,
                              void* d_out, int out_size) {
    const float* enc  = (const float*)d_in[0];
    const float* act  = (const float*)d_in[1];
    const float* tru  = (const float*)d_in[2];
    const float* Wih  = (const float*)d_in[3];
    const float* Whh  = (const float*)d_in[4];
    const float* bih  = (const float*)d_in[5];
    const float* bhh  = (const float*)d_in[6];
    const float* h0   = (const float*)d_in[7];
    const float* fc1w = (const float*)d_in[8];
    const float* fc1b = (const float*)d_in[9];
    const float* fc2w = (const float*)d_in[10];
    const float* fc2b = (const float*)d_in[11];
    float* out = (float*)d_out;

    int mlp_smem = (FCDIM * HH + FCDIM + FCDIM + HH + 8) * 4;
    cudaFuncSetAttribute(mlp_head, cudaFuncAttributeMaxDynamicSharedMemorySize, mlp_smem);

    dim3 g(512, 6, 2);
    gi_gemm<<<g, 256>>>(enc, tru, act, Wih, bih, bhh);
    gru_scan<<<1, 256>>>(Whh, bhh, h0);
    mlp_head<<<512, 256, mlp_smem>>>(fc1w, fc1b, fc2w, fc2b, out);
}